// round 5
// baseline (speedup 1.0000x reference)
#include <cuda_runtime.h>
#include <cstdint>

#define B_    16384
#define CURD  2048
#define FEAT_ 2048
#define HEADS_ 16
#define HDIM  128

#define NTHREADS 256
#define BM 128
#define BN 128
#define BK 32
#define LDSR 36                       // 32 + 4 pad floats per row
#define TILE_F (BM*LDSR)              // floats per buffer per matrix
#define SMEM_BYTES (4*TILE_F*4)       // A(2 bufs) + B(2 bufs)

// ---------------- scratch (device globals; no allocation allowed) ----------
__device__ float g_xs [(size_t)B_*CURD];
__device__ float g_v2s[(size_t)B_*FEAT_];
__device__ float g_v3s[(size_t)B_*FEAT_];
__device__ float g_wq [(size_t)FEAT_*CURD];
__device__ float g_wk2[(size_t)FEAT_*FEAT_];
__device__ float g_wv2[(size_t)FEAT_*FEAT_];
__device__ float g_wk3[(size_t)FEAT_*FEAT_];
__device__ float g_wv3[(size_t)FEAT_*FEAT_];
__device__ float g_wo [(size_t)CURD*FEAT_];
__device__ float g_q  [(size_t)B_*FEAT_];
__device__ float g_kv2[(size_t)B_*2*FEAT_];
__device__ float g_kv3[(size_t)B_*2*FEAT_];
__device__ float g_att[(size_t)B_*FEAT_];
__device__ float g_y  [(size_t)B_*CURD];

// ---------------- helpers ----------------
__device__ __forceinline__ float to_tf32(float x) {
    uint32_t r;
    asm("cvt.rna.tf32.f32 %0, %1;" : "=r"(r) : "f"(x));
    return __uint_as_float(r);
}

__device__ __forceinline__ void cp16(float* s, const float* g) {
    uint32_t sa = (uint32_t)__cvta_generic_to_shared(s);
    asm volatile("cp.async.cg.shared.global [%0], [%1], 16;\n" :: "r"(sa), "l"(g));
}

__device__ __forceinline__ void mma_tf32(float* c, const uint32_t* a, const uint32_t* b) {
    asm volatile(
        "mma.sync.aligned.m16n8k8.row.col.f32.tf32.tf32.f32 "
        "{%0,%1,%2,%3}, {%4,%5,%6,%7}, {%8,%9}, {%0,%1,%2,%3};"
        : "+f"(c[0]), "+f"(c[1]), "+f"(c[2]), "+f"(c[3])
        : "r"(a[0]), "r"(a[1]), "r"(a[2]), "r"(a[3]),
          "r"(b[0]), "r"(b[1]));
}

// ---------------- tf32 pre-rounding (round-to-nearest, kills truncation bias)
__global__ void round_tf32_kernel(const float* __restrict__ in,
                                  float* __restrict__ out, long long n4) {
    long long i  = blockIdx.x * (long long)blockDim.x + threadIdx.x;
    long long st = (long long)gridDim.x * blockDim.x;
    const float4* in4 = (const float4*)in;
    float4* o4 = (float4*)out;
    for (; i < n4; i += st) {
        float4 v = in4[i];
        v.x = to_tf32(v.x); v.y = to_tf32(v.y);
        v.z = to_tf32(v.z); v.w = to_tf32(v.w);
        o4[i] = v;
    }
}

// ---------------- TF32 GEMM:  C[M,N] = A[M,K] @ W[N,K]^T + bias (+res)
// W can be split into two stacked halves (W0 rows [0,Nsplit), W1 the rest),
// so k- and v-projections sharing the same A run as one N=4096 launch.
template<bool RES>
__global__ __launch_bounds__(NTHREADS)
void gemm_tf32_kernel(const float* __restrict__ A,
                      const float* __restrict__ W0,
                      const float* __restrict__ W1,
                      int Nsplit,
                      const float* __restrict__ bias0,
                      const float* __restrict__ bias1,
                      const float* __restrict__ res,
                      float* __restrict__ C,
                      int N, int K) {
    extern __shared__ float smem[];
    float* As = smem;
    float* Bs = smem + 2*TILE_F;

    const int nb = blockIdx.x, mb = blockIdx.y;
    const float* Wp; const float* biasP; int nloc0;
    if (nb*BN < Nsplit) { Wp = W0; biasP = bias0; nloc0 = nb*BN; }
    else                { Wp = W1; biasP = bias1; nloc0 = nb*BN - Nsplit; }

    const int tid  = threadIdx.x;
    const int lrow = tid >> 3;            // 0..31
    const int lc4  = (tid & 7) << 2;      // 0,4,...,28 (floats)
    const float* Ag = A  + (size_t)(mb*BM + lrow)*K + lc4;
    const float* Bg = Wp + (size_t)(nloc0 + lrow)*K + lc4;

    const int warp = tid >> 5, lane = tid & 31;
    const int wm = warp & 3, wn = warp >> 2;     // warp tile 32(M) x 64(N)
    const int qr = lane >> 2, qc = lane & 3;

    float acc[2][8][4];
    #pragma unroll
    for (int i = 0; i < 2; i++)
        #pragma unroll
        for (int j = 0; j < 8; j++)
            #pragma unroll
            for (int l = 0; l < 4; l++) acc[i][j][l] = 0.f;

    const int KT = K / BK;

    // prologue: stage tile 0
    {
        float* Asd = As + lrow*LDSR + lc4;
        float* Bsd = Bs + lrow*LDSR + lc4;
        #pragma unroll
        for (int i = 0; i < 4; i++) {
            cp16(Asd + i*32*LDSR, Ag + (size_t)i*32*K);
            cp16(Bsd + i*32*LDSR, Bg + (size_t)i*32*K);
        }
        asm volatile("cp.async.commit_group;\n" ::);
        asm volatile("cp.async.wait_group 0;\n" ::);
        __syncthreads();
    }

    int buf = 0;
    for (int kt = 0; kt < KT; kt++) {
        if (kt + 1 < KT) {
            int nbuf = buf ^ 1;
            float* Asd = As + nbuf*TILE_F + lrow*LDSR + lc4;
            float* Bsd = Bs + nbuf*TILE_F + lrow*LDSR + lc4;
            const float* Agk = Ag + (kt+1)*BK;
            const float* Bgk = Bg + (kt+1)*BK;
            #pragma unroll
            for (int i = 0; i < 4; i++) {
                cp16(Asd + i*32*LDSR, Agk + (size_t)i*32*K);
                cp16(Bsd + i*32*LDSR, Bgk + (size_t)i*32*K);
            }
            asm volatile("cp.async.commit_group;\n" ::);
        }

        const float* As_ = As + buf*TILE_F;
        const float* Bs_ = Bs + buf*TILE_F;
        #pragma unroll
        for (int ks = 0; ks < BK/8; ks++) {
            const int k = ks*8;
            uint32_t afr[2][4];
            #pragma unroll
            for (int mt = 0; mt < 2; mt++) {
                const float* p = As_ + (wm*32 + mt*16 + qr)*LDSR + k + qc;
                afr[mt][0] = __float_as_uint(p[0]);
                afr[mt][1] = __float_as_uint(p[8*LDSR]);
                afr[mt][2] = __float_as_uint(p[4]);
                afr[mt][3] = __float_as_uint(p[8*LDSR + 4]);
            }
            uint32_t bfr[8][2];
            #pragma unroll
            for (int nt = 0; nt < 8; nt++) {
                const float* p = Bs_ + (wn*64 + nt*8 + qr)*LDSR + k + qc;
                bfr[nt][0] = __float_as_uint(p[0]);
                bfr[nt][1] = __float_as_uint(p[4]);
            }
            #pragma unroll
            for (int mt = 0; mt < 2; mt++)
                #pragma unroll
                for (int nt = 0; nt < 8; nt++)
                    mma_tf32(acc[mt][nt], afr[mt], bfr[nt]);
        }

        asm volatile("cp.async.wait_group 0;\n" ::);
        __syncthreads();
        buf ^= 1;
    }

    // epilogue: bias (+residual), fp32 stores
    float bv0[8], bv1[8];
    #pragma unroll
    for (int nt = 0; nt < 8; nt++) {
        int cl = nloc0 + wn*64 + nt*8 + qc*2;
        bv0[nt] = biasP[cl];
        bv1[nt] = biasP[cl + 1];
    }
    #pragma unroll
    for (int mt = 0; mt < 2; mt++) {
        int r0 = mb*BM + wm*32 + mt*16 + qr;
        #pragma unroll
        for (int nt = 0; nt < 8; nt++) {
            int c0 = nb*BN + wn*64 + nt*8 + qc*2;
            size_t o0 = (size_t)r0*N + c0;
            size_t o1 = o0 + (size_t)8*N;
            float v0 = acc[mt][nt][0] + bv0[nt];
            float v1 = acc[mt][nt][1] + bv1[nt];
            float v2 = acc[mt][nt][2] + bv0[nt];
            float v3 = acc[mt][nt][3] + bv1[nt];
            if (RES) {
                v0 += res[o0]; v1 += res[o0 + 1];
                v2 += res[o1]; v3 += res[o1 + 1];
            }
            *(float2*)(C + o0) = make_float2(v0, v1);
            *(float2*)(C + o1) = make_float2(v2, v3);
        }
    }
}

// ---------------- attention: one warp per (b, h); 2-key softmax -----------
__global__ void attn_kernel(const float* __restrict__ q,
                            const float* __restrict__ kv2,
                            const float* __restrict__ kv3,
                            float* __restrict__ attn,
                            float* __restrict__ wout) {
    int gw   = (blockIdx.x * blockDim.x + threadIdx.x) >> 5;   // b*16 + h
    int lane = threadIdx.x & 31;
    int b = gw >> 4;
    int h = gw & 15;
    size_t qoff = (size_t)b*FEAT_     + h*HDIM + lane*4;
    size_t koff = (size_t)b*(2*FEAT_) + h*HDIM + lane*4;

    float4 qv = *(const float4*)(q   + qoff);
    float4 k2 = *(const float4*)(kv2 + koff);
    float4 k3 = *(const float4*)(kv3 + koff);
    float4 v2 = *(const float4*)(kv2 + koff + FEAT_);
    float4 v3 = *(const float4*)(kv3 + koff + FEAT_);

    float s2 = qv.x*k2.x + qv.y*k2.y + qv.z*k2.z + qv.w*k2.w;
    float s3 = qv.x*k3.x + qv.y*k3.y + qv.z*k3.z + qv.w*k3.w;
    #pragma unroll
    for (int o = 16; o; o >>= 1) {
        s2 += __shfl_xor_sync(0xffffffffu, s2, o);
        s3 += __shfl_xor_sync(0xffffffffu, s3, o);
    }
    const float scale = 0.08838834764831845f;   // 1/sqrt(128)
    s2 *= scale; s3 *= scale;
    float m  = fmaxf(s2, s3);
    float e2 = expf(s2 - m), e3 = expf(s3 - m);
    float inv = 1.f / (e2 + e3);
    float w2 = e2 * inv, w3 = e3 * inv;

    float4 o4;   // tf32-round for the Wo GEMM operand
    o4.x = to_tf32(w2*v2.x + w3*v3.x);
    o4.y = to_tf32(w2*v2.y + w3*v3.y);
    o4.z = to_tf32(w2*v2.z + w3*v3.z);
    o4.w = to_tf32(w2*v2.w + w3*v3.w);
    *(float4*)(attn + qoff) = o4;

    if (lane == 0) {
        wout[(size_t)gw*2]     = w2;
        wout[(size_t)gw*2 + 1] = w3;
    }
}

// ---------------- LayerNorm: one block per row ----------------------------
__global__ void ln_kernel(const float* __restrict__ y,
                          const float* __restrict__ lw,
                          const float* __restrict__ lb,
                          float* __restrict__ out) {
    __shared__ float shs[8], shq[8];
    int row = blockIdx.x, t = threadIdx.x;
    const float4* yr = (const float4*)(y + (size_t)row*CURD);
    float4 a = yr[t];
    float4 b = yr[256 + t];
    float s  = a.x+a.y+a.z+a.w + b.x+b.y+b.z+b.w;
    float qq = a.x*a.x+a.y*a.y+a.z*a.z+a.w*a.w
             + b.x*b.x+b.y*b.y+b.z*b.z+b.w*b.w;
    #pragma unroll
    for (int o = 16; o; o >>= 1) {
        s  += __shfl_xor_sync(0xffffffffu, s,  o);
        qq += __shfl_xor_sync(0xffffffffu, qq, o);
    }
    int warp = t >> 5;
    if ((t & 31) == 0) { shs[warp] = s; shq[warp] = qq; }
    __syncthreads();
    float S = 0.f, Q = 0.f;
    #pragma unroll
    for (int i = 0; i < 8; i++) { S += shs[i]; Q += shq[i]; }
    float mean = S * (1.f/2048.f);
    float inv  = rsqrtf(Q * (1.f/2048.f) - mean*mean + 1e-5f);

    const float4* lw4 = (const float4*)lw;
    const float4* lb4 = (const float4*)lb;
    float4* orow = (float4*)(out + (size_t)row*CURD);
    float4 w, z, o4;
    w = lw4[t];       z = lb4[t];
    o4.x = w.x*(a.x-mean)*inv + z.x;
    o4.y = w.y*(a.y-mean)*inv + z.y;
    o4.z = w.z*(a.z-mean)*inv + z.z;
    o4.w = w.w*(a.w-mean)*inv + z.w;
    orow[t] = o4;
    w = lw4[256+t];   z = lb4[256+t];
    o4.x = w.x*(b.x-mean)*inv + z.x;
    o4.y = w.y*(b.y-mean)*inv + z.y;
    o4.z = w.z*(b.z-mean)*inv + z.z;
    o4.w = w.w*(b.w-mean)*inv + z.w;
    orow[256+t] = o4;
}

// ---------------- launch ---------------------------------------------------
extern "C" void kernel_launch(void* const* d_in, const int* in_sizes, int n_in,
                              void* d_out, int out_size) {
    const float* x   = (const float*)d_in[0];
    const float* v2  = (const float*)d_in[1];
    const float* v3  = (const float*)d_in[2];
    const float* Wq  = (const float*)d_in[3];
    const float* bq  = (const float*)d_in[4];
    const float* Wk2 = (const float*)d_in[5];
    const float* bk2 = (const float*)d_in[6];
    const float* Wk3 = (const float*)d_in[7];
    const float* bk3 = (const float*)d_in[8];
    const float* Wv2 = (const float*)d_in[9];
    const float* bv2 = (const float*)d_in[10];
    const float* Wv3 = (const float*)d_in[11];
    const float* bv3 = (const float*)d_in[12];
    const float* Wo  = (const float*)d_in[13];
    const float* bo  = (const float*)d_in[14];
    const float* lw  = (const float*)d_in[15];
    const float* lb  = (const float*)d_in[16];
    float* out = (float*)d_out;

    float *xs, *v2s, *v3s, *wq, *wk2, *wv2, *wk3, *wv3, *wo;
    float *qb, *kv2, *kv3, *attn, *yb;
    cudaGetSymbolAddress((void**)&xs,  g_xs);
    cudaGetSymbolAddress((void**)&v2s, g_v2s);
    cudaGetSymbolAddress((void**)&v3s, g_v3s);
    cudaGetSymbolAddress((void**)&wq,  g_wq);
    cudaGetSymbolAddress((void**)&wk2, g_wk2);
    cudaGetSymbolAddress((void**)&wv2, g_wv2);
    cudaGetSymbolAddress((void**)&wk3, g_wk3);
    cudaGetSymbolAddress((void**)&wv3, g_wv3);
    cudaGetSymbolAddress((void**)&wo,  g_wo);
    cudaGetSymbolAddress((void**)&qb,  g_q);
    cudaGetSymbolAddress((void**)&kv2, g_kv2);
    cudaGetSymbolAddress((void**)&kv3, g_kv3);
    cudaGetSymbolAddress((void**)&attn,g_att);
    cudaGetSymbolAddress((void**)&yb,  g_y);

    cudaFuncSetAttribute((const void*)gemm_tf32_kernel<false>,
                         cudaFuncAttributeMaxDynamicSharedMemorySize, SMEM_BYTES);
    cudaFuncSetAttribute((const void*)gemm_tf32_kernel<true>,
                         cudaFuncAttributeMaxDynamicSharedMemorySize, SMEM_BYTES);

    const int RG = 2048, RT = 256;
    round_tf32_kernel<<<RG, RT>>>(x,   xs,  (long long)B_*CURD/4);
    round_tf32_kernel<<<RG, RT>>>(v2,  v2s, (long long)B_*FEAT_/4);
    round_tf32_kernel<<<RG, RT>>>(v3,  v3s, (long long)B_*FEAT_/4);
    round_tf32_kernel<<<RG, RT>>>(Wq,  wq,  (long long)FEAT_*CURD/4);
    round_tf32_kernel<<<RG, RT>>>(Wk2, wk2, (long long)FEAT_*FEAT_/4);
    round_tf32_kernel<<<RG, RT>>>(Wv2, wv2, (long long)FEAT_*FEAT_/4);
    round_tf32_kernel<<<RG, RT>>>(Wk3, wk3, (long long)FEAT_*FEAT_/4);
    round_tf32_kernel<<<RG, RT>>>(Wv3, wv3, (long long)FEAT_*FEAT_/4);
    round_tf32_kernel<<<RG, RT>>>(Wo,  wo,  (long long)CURD*FEAT_/4);

    dim3 blk(NTHREADS);
    // q = xs @ Wq^T + bq
    gemm_tf32_kernel<false><<<dim3(FEAT_/BN, B_/BM), blk, SMEM_BYTES>>>(
        xs, wq, wq, FEAT_, bq, bq, nullptr, qb, FEAT_, CURD);
    // [k2 | v2] = v2s @ [Wk2; Wv2]^T + [bk2; bv2]
    gemm_tf32_kernel<false><<<dim3(2*FEAT_/BN, B_/BM), blk, SMEM_BYTES>>>(
        v2s, wk2, wv2, FEAT_, bk2, bv2, nullptr, kv2, 2*FEAT_, FEAT_);
    // [k3 | v3] = v3s @ [Wk3; Wv3]^T + [bk3; bv3]
    gemm_tf32_kernel<false><<<dim3(2*FEAT_/BN, B_/BM), blk, SMEM_BYTES>>>(
        v3s, wk3, wv3, FEAT_, bk3, bv3, nullptr, kv3, 2*FEAT_, FEAT_);

    // attention + attn_weights (written to the tail of d_out)
    size_t woff = (size_t)out_size - (size_t)B_*HEADS_*2;
    attn_kernel<<<B_*HEADS_/8, 256>>>(qb, kv2, kv3, attn, out + woff);

    // y = x + attn @ Wo^T + bo   (residual fused, exact fp32 x)
    gemm_tf32_kernel<true><<<dim3(CURD/BN, B_/BM), blk, SMEM_BYTES>>>(
        attn, wo, wo, CURD, bo, bo, x, yb, CURD, FEAT_);

    // LayerNorm -> d_out
    ln_kernel<<<B_, 256>>>(yb, lw, lb, out);
}